// round 12
// baseline (speedup 1.0000x reference)
#include <cuda_runtime.h>
#include <cuda_bf16.h>
#include <cstdint>

#define DIM 128
#define TILE32 32
#define MAX_N 1000000
#define CHUNK 512

__device__ float g_scores[MAX_N];

// ---------------- smem layout (kernel 1, per CTA ~97KB so 2 CTAs/SM) ----------
// W_hi 32K | W_lo 32K | 2 A-slots (hi 8K + lo 8K each) | bk | c2 | mbar
#define OFF_W_HI   0
#define OFF_W_LO   32768
#define OFF_SLOT0  65536
#define SLOT_BYTES 16384
#define OFF_BK     98304           // b[c] * 2*log2(e)
#define OFF_C2     98816           // -2 * ctx[c]
#define OFF_MBAR   99328           // full[0..1] @ +0, empty[0..1] @ +16
#define SMEM_TOTAL (99328 + 64)

#define N_CONS 128                 // 4 consumer warps
#define N_PROD 64                  // 2 producer warps
#define N_THREADS (N_CONS + N_PROD)

#define K2LOG2E 2.8853900817779268f

// ---------------- helpers ----------------
__device__ __forceinline__ uint32_t smem_to_u32(const void* p) {
    uint32_t a;
    asm("{ .reg .u64 t; cvta.to.shared.u64 t, %1; cvt.u32.u64 %0, t; }"
        : "=r"(a) : "l"(p));
    return a;
}

__device__ __forceinline__ float ex2f(float x) {
    float y; asm("ex2.approx.f32 %0, %1;" : "=f"(y) : "f"(x)); return y;
}
__device__ __forceinline__ float rcpf(float x) {
    float y; asm("rcp.approx.f32 %0, %1;" : "=f"(y) : "f"(x)); return y;
}

// swizzled bf16 tile address: row-major, 256B/row (128 bf16), 16B chunks XOR'd by row&7
__device__ __forceinline__ uint32_t sw_addr(uint32_t base, int row, int kchunk) {
    return base + (uint32_t)row * 256u + (uint32_t)((kchunk ^ (row & 7)) << 4);
}

__device__ __forceinline__ void ldsm4(uint32_t* r, uint32_t addr) {
    asm volatile("ldmatrix.sync.aligned.m8n8.x4.shared.b16 {%0,%1,%2,%3}, [%4];"
        : "=r"(r[0]), "=r"(r[1]), "=r"(r[2]), "=r"(r[3]) : "r"(addr));
}

__device__ __forceinline__ void mma_bf16(float* d, const uint32_t* a, const uint32_t* b) {
    asm volatile(
        "mma.sync.aligned.m16n8k16.row.col.f32.bf16.bf16.f32 "
        "{%0,%1,%2,%3}, {%4,%5,%6,%7}, {%8,%9}, {%0,%1,%2,%3};"
        : "+f"(d[0]), "+f"(d[1]), "+f"(d[2]), "+f"(d[3])
        : "r"(a[0]), "r"(a[1]), "r"(a[2]), "r"(a[3]), "r"(b[0]), "r"(b[1]));
}

#define MBARRIER_INIT(mbar, count) \
    asm volatile("mbarrier.init.shared.b64 [%0], %1;" \
        :: "r"((uint32_t)(mbar)), "r"((uint32_t)(count)) : "memory")

#define MBARRIER_ARRIVE(mbar) \
    asm volatile("mbarrier.arrive.release.cta.shared.b64 _, [%0];" \
        :: "r"((uint32_t)(mbar)) : "memory")

#define MBARRIER_WAIT_PARITY(mbar, parity) do { \
    uint32_t _m = (uint32_t)(mbar), _p = (uint32_t)(parity), _d; \
    asm volatile( \
        "{\n\t.reg .pred p;\n\t" \
        "mbarrier.try_wait.parity.acquire.cta.shared::cta.b64 p, [%1], %2;\n\t" \
        "selp.b32 %0, 1, 0, p;\n\t}" \
        : "=r"(_d) : "r"(_m), "r"(_p) : "memory"); \
    if (!_d) { \
        asm volatile( \
            "{\n\t.reg .pred P1;\n\t" \
            "WL_%=:\n\t" \
            "mbarrier.try_wait.parity.acquire.cta.shared::cta.b64 P1, [%0], %1, 0x989680;\n\t" \
            "@P1 bra.uni WD_%=;\n\t" \
            "bra.uni WL_%=;\n\t" \
            "WD_%=:\n\t}" \
            :: "r"(_m), "r"(_p) : "memory"); \
    } \
} while(0)

union BfU { __nv_bfloat162 b; uint32_t u; };

// Truncation split: hi = top-16-bits bf16 (exact), lo = x - hi (exact fp32) -> bf16 RN.
__device__ __forceinline__ void split_store(char* smem, uint32_t hi_off, uint32_t lo_off,
                                            int r, int q, float4 v) {
    uint32_t xu0 = __float_as_uint(v.x), xu1 = __float_as_uint(v.y);
    uint32_t xu2 = __float_as_uint(v.z), xu3 = __float_as_uint(v.w);
    uint32_t hi01 = (xu0 >> 16) | (xu1 & 0xFFFF0000u);
    uint32_t hi23 = (xu2 >> 16) | (xu3 & 0xFFFF0000u);
    float l0f = v.x - __uint_as_float(xu0 & 0xFFFF0000u);
    float l1f = v.y - __uint_as_float(xu1 & 0xFFFF0000u);
    float l2f = v.z - __uint_as_float(xu2 & 0xFFFF0000u);
    float l3f = v.w - __uint_as_float(xu3 & 0xFFFF0000u);
    BfU lo01, lo23;
    lo01.b = __floats2bfloat162_rn(l0f, l1f);
    lo23.b = __floats2bfloat162_rn(l2f, l3f);
    uint32_t boff = (uint32_t)r * 256u + (uint32_t)(((q >> 1) ^ (r & 7)) << 4)
                  + (uint32_t)((q & 1) << 3);
    *(uint2*)(smem + hi_off + boff) = make_uint2(hi01, hi23);
    *(uint2*)(smem + lo_off + boff) = make_uint2(lo01.u, lo23.u);
}

// ================= Kernel 1: 2 CTAs/SM, warp-specialized, in-warp pipeline ======
// Per CTA: warps 0-3 consumers (warp w: m16 block w&1, n64 half w>>1),
// warps 4-5 producers. m32 tiles, 2-slot A ring. Two CTAs per SM drift
// independently so one CTA's HMMA fills the other's bubbles.
__global__ void __launch_bounds__(N_THREADS, 2)
score_kernel(const float* __restrict__ h, const float* __restrict__ W,
             const float* __restrict__ b, const float* __restrict__ ctx, int n)
{
    extern __shared__ char smem[];
    uint32_t sb = smem_to_u32(smem);
    int tid = threadIdx.x;
    int wid = tid >> 5, lane = tid & 31;

    // ---- prologue: W split (swizzled), transformed b/ctx, mbarriers ----
    for (int idx = tid; idx < 128 * 32; idx += N_THREADS) {
        int r = idx >> 5, q = idx & 31;
        float4 v = *(const float4*)(W + (size_t)r * DIM + q * 4);
        split_store(smem, OFF_W_HI, OFF_W_LO, r, q, v);
    }
    if (tid < DIM) {
        ((float*)(smem + OFF_BK))[tid] = b[tid] * K2LOG2E;
        ((float*)(smem + OFF_C2))[tid] = -2.0f * ctx[tid];
    }
    if (tid == 0) {
        #pragma unroll
        for (int s = 0; s < 2; s++) {
            MBARRIER_INIT(sb + OFF_MBAR + s * 8, N_PROD);        // full[s]
            MBARRIER_INIT(sb + OFF_MBAR + 16 + s * 8, N_CONS);   // empty[s]
        }
    }
    __syncthreads();

    int ntiles = (n + TILE32 - 1) / TILE32;

    if (wid >= 4) {
        // ================== PRODUCER (2 warps, 64 threads) ==================
        int ptid = tid - N_CONS;            // 0..63
        int ph[2] = {1, 1};                 // fresh-barrier: parity-1 wait passes
        for (int j = 0; ; j++) {
            long long tg = (long long)blockIdx.x + (long long)j * gridDim.x;
            if (tg >= ntiles) break;
            int slot = j & 1;
            MBARRIER_WAIT_PARITY(sb + OFF_MBAR + 16 + slot * 8, ph[slot]);
            ph[slot] ^= 1;
            uint32_t a_hi = OFF_SLOT0 + slot * SLOT_BYTES;
            uint32_t a_lo = a_hi + 8192;
            int m0 = (int)tg * TILE32;
            int valid = min(TILE32, n - m0);
            const float4* src = (const float4*)(h + (size_t)m0 * DIM);
            #pragma unroll
            for (int it = 0; it < 16; it++) {
                int chunk = ptid + it * N_PROD;   // 1024 chunks of 16B
                int r = chunk >> 5, q = chunk & 31;
                float4 v = (r < valid) ? __ldcs(src + chunk)
                                       : make_float4(0.f, 0.f, 0.f, 0.f);
                split_store(smem, a_hi, a_lo, r, q, v);
            }
            MBARRIER_ARRIVE(sb + OFF_MBAR + slot * 8);   // full[slot]
        }
    } else {
        // ================== CONSUMER (4 warps) ==================
        const float* bkp = (const float*)(smem + OFF_BK);
        const float* c2p = (const float*)(smem + OFF_C2);
        int mb  = wid & 1;        // m16 block within m32 tile
        int nbk = wid >> 1;       // n64 half

        // csum: sum of ctx over this thread's 16 columns in its n64 half
        float csum = 0.f;
        {
            int cb = nbk * 64 + (lane & 3) * 2;
            #pragma unroll
            for (int j = 0; j < 8; j++)
                csum += ctx[cb + j * 8] + ctx[cb + j * 8 + 1];
        }

        int arow   = mb * 16 + (lane & 15);
        int brow0  = nbk * 64 + (lane & 7) + ((lane >> 4) << 3);
        int bk_sel = (lane >> 3) & 1;

        float cur[8][4], prev[8][4];
        #pragma unroll
        for (int jj = 0; jj < 8; jj++)
            #pragma unroll
            for (int e = 0; e < 4; e++) prev[jj][e] = 0.f;
        int  m_prev = 0;
        bool have_prev = false;
        int  ph[2] = {0, 0};

        for (int j = 0; ; j++) {
            long long tg = (long long)blockIdx.x + (long long)j * gridDim.x;
            if (tg >= ntiles) break;
            int slot = j & 1;
            MBARRIER_WAIT_PARITY(sb + OFF_MBAR + slot * 8, ph[slot]);   // full
            ph[slot] ^= 1;
            uint32_t a_hi_b = OFF_SLOT0 + slot * SLOT_BYTES;
            uint32_t a_lo_b = a_hi_b + 8192;

            #pragma unroll
            for (int jj = 0; jj < 8; jj++)
                #pragma unroll
                for (int e = 0; e < 4; e++) cur[jj][e] = 0.f;

            float s0 = csum, s1 = csum;   // epilogue of PREVIOUS tile

            #pragma unroll
            for (int ks = 0; ks < 8; ks++) {
                // ---- MMA work for current tile, this ks ----
                uint32_t a_hi[4], a_lo[4];
                int akch = ks * 2 + (lane >> 4);
                ldsm4(a_hi, sw_addr(sb + a_hi_b, arow, akch));
                ldsm4(a_lo, sw_addr(sb + a_lo_b, arow, akch));
                int bkch = ks * 2 + bk_sel;
                #pragma unroll
                for (int p = 0; p < 4; p++) {
                    uint32_t bh[4], bl[4];
                    int br = brow0 + p * 16;
                    ldsm4(bh, sw_addr(sb + OFF_W_HI, br, bkch));
                    ldsm4(bl, sw_addr(sb + OFF_W_LO, br, bkch));
                    mma_bf16(cur[2 * p],     a_hi, bh);
                    mma_bf16(cur[2 * p],     a_lo, bh);
                    mma_bf16(cur[2 * p],     a_hi, bl);
                    mma_bf16(cur[2 * p + 1], a_hi, bh + 2);
                    mma_bf16(cur[2 * p + 1], a_lo, bh + 2);
                    mma_bf16(cur[2 * p + 1], a_hi, bl + 2);
                }

                // ---- interleaved epilogue chunk jj=ks of previous tile ----
                {
                    int c0 = nbk * 64 + ks * 8 + (lane & 3) * 2;
                    float bk0 = bkp[c0], bk1 = bkp[c0 + 1];
                    float c20 = c2p[c0], c21 = c2p[c0 + 1];
                    s0 += rcpf(1.0f + ex2f(fmaf(prev[ks][0], K2LOG2E, bk0))) * c20
                        + rcpf(1.0f + ex2f(fmaf(prev[ks][1], K2LOG2E, bk1))) * c21;
                    s1 += rcpf(1.0f + ex2f(fmaf(prev[ks][2], K2LOG2E, bk0))) * c20
                        + rcpf(1.0f + ex2f(fmaf(prev[ks][3], K2LOG2E, bk1))) * c21;
                }
            }

            // release stage (epilogue used only registers + const smem)
            MBARRIER_ARRIVE(sb + OFF_MBAR + 16 + slot * 8);   // empty

            // finish previous tile's scores: quad reduce + RED combine n-halves
            s0 += __shfl_xor_sync(0xffffffffu, s0, 1);
            s0 += __shfl_xor_sync(0xffffffffu, s0, 2);
            s1 += __shfl_xor_sync(0xffffffffu, s1, 1);
            s1 += __shfl_xor_sync(0xffffffffu, s1, 2);
            if (have_prev && (lane & 3) == 0) {
                int m = m_prev + mb * 16 + (lane >> 2);
                if (m < n)     atomicAdd(&g_scores[m], s0);
                if (m + 8 < n) atomicAdd(&g_scores[m + 8], s1);
            }

            #pragma unroll
            for (int jj = 0; jj < 8; jj++)
                #pragma unroll
                for (int e = 0; e < 4; e++) prev[jj][e] = cur[jj][e];
            m_prev = (int)tg * TILE32;
            have_prev = true;
        }

        // drain: epilogue of the final tile
        if (have_prev) {
            float s0 = csum, s1 = csum;
            #pragma unroll
            for (int jj = 0; jj < 8; jj++) {
                int c0 = nbk * 64 + jj * 8 + (lane & 3) * 2;
                float bk0 = bkp[c0], bk1 = bkp[c0 + 1];
                float c20 = c2p[c0], c21 = c2p[c0 + 1];
                s0 += rcpf(1.0f + ex2f(fmaf(prev[jj][0], K2LOG2E, bk0))) * c20
                    + rcpf(1.0f + ex2f(fmaf(prev[jj][1], K2LOG2E, bk1))) * c21;
                s1 += rcpf(1.0f + ex2f(fmaf(prev[jj][2], K2LOG2E, bk0))) * c20
                    + rcpf(1.0f + ex2f(fmaf(prev[jj][3], K2LOG2E, bk1))) * c21;
            }
            s0 += __shfl_xor_sync(0xffffffffu, s0, 1);
            s0 += __shfl_xor_sync(0xffffffffu, s0, 2);
            s1 += __shfl_xor_sync(0xffffffffu, s1, 1);
            s1 += __shfl_xor_sync(0xffffffffu, s1, 2);
            if ((lane & 3) == 0) {
                int m = m_prev + mb * 16 + (lane >> 2);
                if (m < n)     atomicAdd(&g_scores[m], s0);
                if (m + 8 < n) atomicAdd(&g_scores[m + 8], s1);
            }
        }
    }
}

// ======= Kernel 2a: per-segment softmax stats -> normalized alpha; zero h_file =======
__global__ void __launch_bounds__(128)
seg_stats_kernel(const int* __restrict__ blk, float* __restrict__ h_file,
                 float* __restrict__ alpha)
{
    int k = blockIdx.x;
    int s = blk[k], e = blk[k + 1];
    int t = threadIdx.x, wid = t >> 5, lid = t & 31;
    __shared__ float red[4];

    h_file[(size_t)k * DIM + t] = 0.f;   // atomics accumulate later
    if (e - s <= 0) return;

    float m = -3.402823466e38f;
    for (int i = s + t; i < e; i += 128) m = fmaxf(m, g_scores[i]);
    #pragma unroll
    for (int o = 16; o; o >>= 1) m = fmaxf(m, __shfl_xor_sync(0xffffffffu, m, o));
    if (lid == 0) red[wid] = m;
    __syncthreads();
    m = fmaxf(fmaxf(red[0], red[1]), fmaxf(red[2], red[3]));
    __syncthreads();

    float sum = 0.f;
    for (int i = s + t; i < e; i += 128) {
        float ev = __expf(g_scores[i] - m);
        alpha[i] = ev;
        sum += ev;
    }
    #pragma unroll
    for (int o = 16; o; o >>= 1) sum += __shfl_xor_sync(0xffffffffu, sum, o);
    if (lid == 0) red[wid] = sum;
    __syncthreads();
    sum = red[0] + red[1] + red[2] + red[3];
    float inv = 1.0f / sum;

    // normalize in place (each thread rescales exactly what it wrote)
    for (int j = s + t; j < e; j += 128) alpha[j] *= inv;
}

// ======= Kernel 2b: uniform-chunk weighted accumulation (float4, 4 rows/iter) ===
__global__ void __launch_bounds__(128)
accum_kernel(const float* __restrict__ h, const int* __restrict__ blk,
             const float* __restrict__ alpha, float* __restrict__ h_file,
             int n, int B)
{
    int r0 = blockIdx.x * CHUNK;
    int r1 = min(n, r0 + CHUNK);
    if (r0 >= r1) return;
    int t = threadIdx.x;
    int wq = t >> 5;          // 0..3: row offset within 4-row group
    int q  = t & 31;          // float4 column index

    int lo = 0, hi = B - 1;
    while (lo < hi) {
        int mid = (lo + hi + 1) >> 1;
        if (blk[mid] <= r0) lo = mid; else hi = mid - 1;
    }
    int k = lo;
    int nend = blk[k + 1];

    float4 acc = make_float4(0.f, 0.f, 0.f, 0.f);
    int i = r0;
    while (true) {
        int stop = min(r1, nend);
        #pragma unroll 4
        for (; i + 4 <= stop; i += 4) {
            int r = i + wq;
            float a = __ldcs(alpha + r);
            float4 hv = __ldcs((const float4*)(h + (size_t)r * DIM) + q);
            acc.x = fmaf(a, hv.x, acc.x);
            acc.y = fmaf(a, hv.y, acc.y);
            acc.z = fmaf(a, hv.z, acc.z);
            acc.w = fmaf(a, hv.w, acc.w);
        }
        if (i < stop) {
            int r = i + wq;
            if (r < stop) {
                float a = __ldcs(alpha + r);
                float4 hv = __ldcs((const float4*)(h + (size_t)r * DIM) + q);
                acc.x = fmaf(a, hv.x, acc.x);
                acc.y = fmaf(a, hv.y, acc.y);
                acc.z = fmaf(a, hv.z, acc.z);
                acc.w = fmaf(a, hv.w, acc.w);
            }
            i = stop;
        }
        if (stop < r1) {
            float* dst = h_file + (size_t)k * DIM + q * 4;
            atomicAdd(dst + 0, acc.x);
            atomicAdd(dst + 1, acc.y);
            atomicAdd(dst + 2, acc.z);
            atomicAdd(dst + 3, acc.w);
            acc = make_float4(0.f, 0.f, 0.f, 0.f);
            do { k++; } while (blk[k + 1] <= stop);
            nend = blk[k + 1];
        } else break;
    }
    float* dst = h_file + (size_t)k * DIM + q * 4;
    atomicAdd(dst + 0, acc.x);
    atomicAdd(dst + 1, acc.y);
    atomicAdd(dst + 2, acc.z);
    atomicAdd(dst + 3, acc.w);
}

// ================= launch =================
extern "C" void kernel_launch(void* const* d_in, const int* in_sizes, int n_in,
                              void* d_out, int out_size)
{
    const float* h   = (const float*)d_in[0];
    const float* W   = (const float*)d_in[1];
    const float* b   = (const float*)d_in[2];
    const float* ctx = (const float*)d_in[3];
    const int*   blk = (const int*)d_in[4];

    int n = in_sizes[0] / DIM;
    if (n > MAX_N) n = MAX_N;
    int B = in_sizes[4] - 1;

    float* out    = (float*)d_out;
    float* h_file = out;
    float* alpha  = out + (size_t)B * DIM;

    cudaFuncSetAttribute(score_kernel,
                         cudaFuncAttributeMaxDynamicSharedMemorySize, SMEM_TOTAL);

    int dev = 0, nsm = 148;
    cudaGetDevice(&dev);
    cudaDeviceGetAttribute(&nsm, cudaDevAttrMultiProcessorCount, dev);

    // zero the score accumulator (RED targets); graph-capturable memset node
    void* sc_ptr = nullptr;
    cudaGetSymbolAddress(&sc_ptr, g_scores);
    cudaMemsetAsync(sc_ptr, 0, (size_t)n * sizeof(float));

    int ntiles = (n + TILE32 - 1) / TILE32;
    int grid1 = 2 * nsm;                    // 2 CTAs per SM
    if (grid1 > ntiles) grid1 = ntiles;

    score_kernel<<<grid1, N_THREADS, SMEM_TOTAL>>>(h, W, b, ctx, n);
    seg_stats_kernel<<<B, 128>>>(blk, h_file, alpha);
    int gridB = (n + CHUNK - 1) / CHUNK;
    accum_kernel<<<gridB, 128>>>(h, blk, alpha, h_file, n, B);
}

// round 13
// speedup vs baseline: 1.0129x; 1.0129x over previous
#include <cuda_runtime.h>
#include <cuda_bf16.h>
#include <cstdint>

#define DIM 128
#define TILE96 96
#define MAX_N 1000000
#define CHUNK 512

__device__ float g_scores[MAX_N];

// ---------------- smem layout (kernel 1) ----------------
// W_hi 32K | W_lo 32K | 2 A-slots (hi 24K + lo 24K each) | bk | c2 | mbar
#define OFF_W_HI   0
#define OFF_W_LO   32768
#define OFF_SLOT0  65536
#define SLOT_BYTES 49152
#define OFF_BK     163840          // b[c] * 2*log2(e)
#define OFF_C2     164352          // -2 * ctx[c]
#define OFF_MBAR   164864          // full[0..1] @ +0, empty[0..1] @ +16
#define SMEM_TOTAL (164864 + 64)

#define N_CONS 384                 // 12 consumer warps (3 per SMSP)
#define N_PROD 128                 // 4 producer warps
#define N_THREADS (N_CONS + N_PROD)

#define K2LOG2E 2.8853900817779268f

// ---------------- helpers ----------------
__device__ __forceinline__ uint32_t smem_to_u32(const void* p) {
    uint32_t a;
    asm("{ .reg .u64 t; cvta.to.shared.u64 t, %1; cvt.u32.u64 %0, t; }"
        : "=r"(a) : "l"(p));
    return a;
}

__device__ __forceinline__ float ex2f(float x) {
    float y; asm("ex2.approx.f32 %0, %1;" : "=f"(y) : "f"(x)); return y;
}
__device__ __forceinline__ float rcpf(float x) {
    float y; asm("rcp.approx.f32 %0, %1;" : "=f"(y) : "f"(x)); return y;
}

// swizzled bf16 tile address: row-major, 256B/row (128 bf16), 16B chunks XOR'd by row&7
__device__ __forceinline__ uint32_t sw_addr(uint32_t base, int row, int kchunk) {
    return base + (uint32_t)row * 256u + (uint32_t)((kchunk ^ (row & 7)) << 4);
}

__device__ __forceinline__ void ldsm4(uint32_t* r, uint32_t addr) {
    asm volatile("ldmatrix.sync.aligned.m8n8.x4.shared.b16 {%0,%1,%2,%3}, [%4];"
        : "=r"(r[0]), "=r"(r[1]), "=r"(r[2]), "=r"(r[3]) : "r"(addr));
}

__device__ __forceinline__ void mma_bf16(float* d, const uint32_t* a, const uint32_t* b) {
    asm volatile(
        "mma.sync.aligned.m16n8k16.row.col.f32.bf16.bf16.f32 "
        "{%0,%1,%2,%3}, {%4,%5,%6,%7}, {%8,%9}, {%0,%1,%2,%3};"
        : "+f"(d[0]), "+f"(d[1]), "+f"(d[2]), "+f"(d[3])
        : "r"(a[0]), "r"(a[1]), "r"(a[2]), "r"(a[3]), "r"(b[0]), "r"(b[1]));
}

#define MBARRIER_INIT(mbar, count) \
    asm volatile("mbarrier.init.shared.b64 [%0], %1;" \
        :: "r"((uint32_t)(mbar)), "r"((uint32_t)(count)) : "memory")

#define MBARRIER_ARRIVE(mbar) \
    asm volatile("mbarrier.arrive.release.cta.shared.b64 _, [%0];" \
        :: "r"((uint32_t)(mbar)) : "memory")

#define MBARRIER_WAIT_PARITY(mbar, parity) do { \
    uint32_t _m = (uint32_t)(mbar), _p = (uint32_t)(parity), _d; \
    asm volatile( \
        "{\n\t.reg .pred p;\n\t" \
        "mbarrier.try_wait.parity.acquire.cta.shared::cta.b64 p, [%1], %2;\n\t" \
        "selp.b32 %0, 1, 0, p;\n\t}" \
        : "=r"(_d) : "r"(_m), "r"(_p) : "memory"); \
    if (!_d) { \
        asm volatile( \
            "{\n\t.reg .pred P1;\n\t" \
            "WL_%=:\n\t" \
            "mbarrier.try_wait.parity.acquire.cta.shared::cta.b64 P1, [%0], %1, 0x989680;\n\t" \
            "@P1 bra.uni WD_%=;\n\t" \
            "bra.uni WL_%=;\n\t" \
            "WD_%=:\n\t}" \
            :: "r"(_m), "r"(_p) : "memory"); \
    } \
} while(0)

union BfU { __nv_bfloat162 b; uint32_t u; };

// Truncation split: hi = top-16-bits bf16 (exact), lo = x - hi (exact fp32) -> bf16 RN.
__device__ __forceinline__ void split_store(char* smem, uint32_t hi_off, uint32_t lo_off,
                                            int r, int q, float4 v) {
    uint32_t xu0 = __float_as_uint(v.x), xu1 = __float_as_uint(v.y);
    uint32_t xu2 = __float_as_uint(v.z), xu3 = __float_as_uint(v.w);
    uint32_t hi01 = (xu0 >> 16) | (xu1 & 0xFFFF0000u);
    uint32_t hi23 = (xu2 >> 16) | (xu3 & 0xFFFF0000u);
    float l0f = v.x - __uint_as_float(xu0 & 0xFFFF0000u);
    float l1f = v.y - __uint_as_float(xu1 & 0xFFFF0000u);
    float l2f = v.z - __uint_as_float(xu2 & 0xFFFF0000u);
    float l3f = v.w - __uint_as_float(xu3 & 0xFFFF0000u);
    BfU lo01, lo23;
    lo01.b = __floats2bfloat162_rn(l0f, l1f);
    lo23.b = __floats2bfloat162_rn(l2f, l3f);
    uint32_t boff = (uint32_t)r * 256u + (uint32_t)(((q >> 1) ^ (r & 7)) << 4)
                  + (uint32_t)((q & 1) << 3);
    *(uint2*)(smem + hi_off + boff) = make_uint2(hi01, hi23);
    *(uint2*)(smem + lo_off + boff) = make_uint2(lo01.u, lo23.u);
}

// ================= Kernel 1: 16 warps, 3 consumer warps per SMSP ================
// Consumers (warps 0-11): warp w owns m16 block (w>>1) of the m96 tile, n64 half
// (w&1). 3 consumer warps per SMSP cover ldsm->mma latency so the tensor pipe
// stays fed. Producers (warps 12-15): LDG.cs -> split -> STS into 2-slot ring.
__global__ void __launch_bounds__(N_THREADS, 1)
score_kernel(const float* __restrict__ h, const float* __restrict__ W,
             const float* __restrict__ b, const float* __restrict__ ctx, int n)
{
    extern __shared__ char smem[];
    uint32_t sb = smem_to_u32(smem);
    int tid = threadIdx.x;
    int wid = tid >> 5, lane = tid & 31;

    // ---- prologue: W split (swizzled), transformed b/ctx, mbarriers ----
    for (int idx = tid; idx < 128 * 32; idx += N_THREADS) {
        int r = idx >> 5, q = idx & 31;
        float4 v = *(const float4*)(W + (size_t)r * DIM + q * 4);
        split_store(smem, OFF_W_HI, OFF_W_LO, r, q, v);
    }
    if (tid < DIM) {
        ((float*)(smem + OFF_BK))[tid] = b[tid] * K2LOG2E;
        ((float*)(smem + OFF_C2))[tid] = -2.0f * ctx[tid];
    }
    if (tid == 0) {
        #pragma unroll
        for (int s = 0; s < 2; s++) {
            MBARRIER_INIT(sb + OFF_MBAR + s * 8, N_PROD);        // full[s]
            MBARRIER_INIT(sb + OFF_MBAR + 16 + s * 8, N_CONS);   // empty[s]
        }
    }
    __syncthreads();

    int ntiles = (n + TILE96 - 1) / TILE96;

    if (wid >= 12) {
        // ================== PRODUCER (4 warps, 128 threads) ==================
        int ptid = tid - N_CONS;            // 0..127
        int ph[2] = {1, 1};                 // fresh-barrier: parity-1 wait passes
        for (int j = 0; ; j++) {
            long long tg = (long long)blockIdx.x + (long long)j * gridDim.x;
            if (tg >= ntiles) break;
            int slot = j & 1;
            MBARRIER_WAIT_PARITY(sb + OFF_MBAR + 16 + slot * 8, ph[slot]);
            ph[slot] ^= 1;
            uint32_t a_hi = OFF_SLOT0 + slot * SLOT_BYTES;
            uint32_t a_lo = a_hi + 24576;
            int m0 = (int)tg * TILE96;
            int valid = min(TILE96, n - m0);
            const float4* src = (const float4*)(h + (size_t)m0 * DIM);
            #pragma unroll
            for (int it = 0; it < 24; it++) {
                int chunk = ptid + it * N_PROD;   // 3072 chunks of 16B
                int r = chunk >> 5, q = chunk & 31;
                float4 v = (r < valid) ? __ldcs(src + chunk)
                                       : make_float4(0.f, 0.f, 0.f, 0.f);
                split_store(smem, a_hi, a_lo, r, q, v);
            }
            MBARRIER_ARRIVE(sb + OFF_MBAR + slot * 8);   // full[slot]
        }
    } else {
        // ================== CONSUMER (12 warps) ==================
        const float* bkp = (const float*)(smem + OFF_BK);
        const float* c2p = (const float*)(smem + OFF_C2);
        int mb  = wid >> 1;       // m16 block within m96 tile (0..5)
        int nbk = wid & 1;        // n64 half

        // csum: sum of ctx over this thread's 16 columns in its n64 half
        float csum = 0.f;
        {
            int cb = nbk * 64 + (lane & 3) * 2;
            #pragma unroll
            for (int j = 0; j < 8; j++)
                csum += ctx[cb + j * 8] + ctx[cb + j * 8 + 1];
        }

        int arow   = mb * 16 + (lane & 15);
        int brow0  = nbk * 64 + (lane & 7) + ((lane >> 4) << 3);
        int bk_sel = (lane >> 3) & 1;
        int ph[2] = {0, 0};

        for (int j = 0; ; j++) {
            long long tg = (long long)blockIdx.x + (long long)j * gridDim.x;
            if (tg >= ntiles) break;
            int slot = j & 1;
            MBARRIER_WAIT_PARITY(sb + OFF_MBAR + slot * 8, ph[slot]);   // full
            ph[slot] ^= 1;
            uint32_t a_hi_b = OFF_SLOT0 + slot * SLOT_BYTES;
            uint32_t a_lo_b = a_hi_b + 24576;

            float acc[8][4];
            #pragma unroll
            for (int jj = 0; jj < 8; jj++)
                #pragma unroll
                for (int e = 0; e < 4; e++) acc[jj][e] = 0.f;

            #pragma unroll
            for (int ks = 0; ks < 8; ks++) {
                uint32_t a_hi[4], a_lo[4];
                int akch = ks * 2 + (lane >> 4);
                ldsm4(a_hi, sw_addr(sb + a_hi_b, arow, akch));
                ldsm4(a_lo, sw_addr(sb + a_lo_b, arow, akch));
                int bkch = ks * 2 + bk_sel;
                #pragma unroll
                for (int p = 0; p < 4; p++) {
                    uint32_t bh[4], bl[4];
                    int br = brow0 + p * 16;
                    ldsm4(bh, sw_addr(sb + OFF_W_HI, br, bkch));
                    ldsm4(bl, sw_addr(sb + OFF_W_LO, br, bkch));
                    mma_bf16(acc[2 * p],     a_hi, bh);
                    mma_bf16(acc[2 * p],     a_lo, bh);
                    mma_bf16(acc[2 * p],     a_hi, bl);
                    mma_bf16(acc[2 * p + 1], a_hi, bh + 2);
                    mma_bf16(acc[2 * p + 1], a_lo, bh + 2);
                    mma_bf16(acc[2 * p + 1], a_hi, bl + 2);
                }
            }

            // release slot (epilogue uses only registers + const smem)
            MBARRIER_ARRIVE(sb + OFF_MBAR + 16 + slot * 8);   // empty

            // epilogue: tanh(x) = 1 - 2/(1+e^{2x}); 3 FFMA + EX2 + RCP per elem
            float s0 = csum, s1 = csum;
            #pragma unroll
            for (int jj = 0; jj < 8; jj++) {
                int c0 = nbk * 64 + jj * 8 + (lane & 3) * 2;
                float bk0 = bkp[c0], bk1 = bkp[c0 + 1];
                float c20 = c2p[c0], c21 = c2p[c0 + 1];
                s0 += rcpf(1.0f + ex2f(fmaf(acc[jj][0], K2LOG2E, bk0))) * c20
                    + rcpf(1.0f + ex2f(fmaf(acc[jj][1], K2LOG2E, bk1))) * c21;
                s1 += rcpf(1.0f + ex2f(fmaf(acc[jj][2], K2LOG2E, bk0))) * c20
                    + rcpf(1.0f + ex2f(fmaf(acc[jj][3], K2LOG2E, bk1))) * c21;
            }
            s0 += __shfl_xor_sync(0xffffffffu, s0, 1);
            s0 += __shfl_xor_sync(0xffffffffu, s0, 2);
            s1 += __shfl_xor_sync(0xffffffffu, s1, 1);
            s1 += __shfl_xor_sync(0xffffffffu, s1, 2);
            if ((lane & 3) == 0) {
                int m = (int)tg * TILE96 + mb * 16 + (lane >> 2);
                if (m < n)     atomicAdd(&g_scores[m], s0);
                if (m + 8 < n) atomicAdd(&g_scores[m + 8], s1);
            }
        }
    }
}

// ======= Kernel 2a: per-segment softmax stats -> normalized alpha; zero h_file =======
__global__ void __launch_bounds__(128)
seg_stats_kernel(const int* __restrict__ blk, float* __restrict__ h_file,
                 float* __restrict__ alpha)
{
    int k = blockIdx.x;
    int s = blk[k], e = blk[k + 1];
    int t = threadIdx.x, wid = t >> 5, lid = t & 31;
    __shared__ float red[4];

    h_file[(size_t)k * DIM + t] = 0.f;   // atomics accumulate later
    if (e - s <= 0) return;

    float m = -3.402823466e38f;
    for (int i = s + t; i < e; i += 128) m = fmaxf(m, g_scores[i]);
    #pragma unroll
    for (int o = 16; o; o >>= 1) m = fmaxf(m, __shfl_xor_sync(0xffffffffu, m, o));
    if (lid == 0) red[wid] = m;
    __syncthreads();
    m = fmaxf(fmaxf(red[0], red[1]), fmaxf(red[2], red[3]));
    __syncthreads();

    float sum = 0.f;
    for (int i = s + t; i < e; i += 128) {
        float ev = __expf(g_scores[i] - m);
        alpha[i] = ev;
        sum += ev;
    }
    #pragma unroll
    for (int o = 16; o; o >>= 1) sum += __shfl_xor_sync(0xffffffffu, sum, o);
    if (lid == 0) red[wid] = sum;
    __syncthreads();
    sum = red[0] + red[1] + red[2] + red[3];
    float inv = 1.0f / sum;

    // normalize in place (each thread rescales exactly what it wrote)
    for (int j = s + t; j < e; j += 128) alpha[j] *= inv;
}

// ======= Kernel 2b: uniform-chunk weighted accumulation (float4, 4 rows/iter) ===
__global__ void __launch_bounds__(128)
accum_kernel(const float* __restrict__ h, const int* __restrict__ blk,
             const float* __restrict__ alpha, float* __restrict__ h_file,
             int n, int B)
{
    int r0 = blockIdx.x * CHUNK;
    int r1 = min(n, r0 + CHUNK);
    if (r0 >= r1) return;
    int t = threadIdx.x;
    int wq = t >> 5;          // 0..3: row offset within 4-row group
    int q  = t & 31;          // float4 column index

    int lo = 0, hi = B - 1;
    while (lo < hi) {
        int mid = (lo + hi + 1) >> 1;
        if (blk[mid] <= r0) lo = mid; else hi = mid - 1;
    }
    int k = lo;
    int nend = blk[k + 1];

    float4 acc = make_float4(0.f, 0.f, 0.f, 0.f);
    int i = r0;
    while (true) {
        int stop = min(r1, nend);
        #pragma unroll 4
        for (; i + 4 <= stop; i += 4) {
            int r = i + wq;
            float a = __ldcs(alpha + r);
            float4 hv = __ldcs((const float4*)(h + (size_t)r * DIM) + q);
            acc.x = fmaf(a, hv.x, acc.x);
            acc.y = fmaf(a, hv.y, acc.y);
            acc.z = fmaf(a, hv.z, acc.z);
            acc.w = fmaf(a, hv.w, acc.w);
        }
        if (i < stop) {
            int r = i + wq;
            if (r < stop) {
                float a = __ldcs(alpha + r);
                float4 hv = __ldcs((const float4*)(h + (size_t)r * DIM) + q);
                acc.x = fmaf(a, hv.x, acc.x);
                acc.y = fmaf(a, hv.y, acc.y);
                acc.z = fmaf(a, hv.z, acc.z);
                acc.w = fmaf(a, hv.w, acc.w);
            }
            i = stop;
        }
        if (stop < r1) {
            float* dst = h_file + (size_t)k * DIM + q * 4;
            atomicAdd(dst + 0, acc.x);
            atomicAdd(dst + 1, acc.y);
            atomicAdd(dst + 2, acc.z);
            atomicAdd(dst + 3, acc.w);
            acc = make_float4(0.f, 0.f, 0.f, 0.f);
            do { k++; } while (blk[k + 1] <= stop);
            nend = blk[k + 1];
        } else break;
    }
    float* dst = h_file + (size_t)k * DIM + q * 4;
    atomicAdd(dst + 0, acc.x);
    atomicAdd(dst + 1, acc.y);
    atomicAdd(dst + 2, acc.z);
    atomicAdd(dst + 3, acc.w);
}

// ================= launch =================
extern "C" void kernel_launch(void* const* d_in, const int* in_sizes, int n_in,
                              void* d_out, int out_size)
{
    const float* h   = (const float*)d_in[0];
    const float* W   = (const float*)d_in[1];
    const float* b   = (const float*)d_in[2];
    const float* ctx = (const float*)d_in[3];
    const int*   blk = (const int*)d_in[4];

    int n = in_sizes[0] / DIM;
    if (n > MAX_N) n = MAX_N;
    int B = in_sizes[4] - 1;

    float* out    = (float*)d_out;
    float* h_file = out;
    float* alpha  = out + (size_t)B * DIM;

    cudaFuncSetAttribute(score_kernel,
                         cudaFuncAttributeMaxDynamicSharedMemorySize, SMEM_TOTAL);

    int dev = 0, nsm = 148;
    cudaGetDevice(&dev);
    cudaDeviceGetAttribute(&nsm, cudaDevAttrMultiProcessorCount, dev);

    // zero the score accumulator (RED targets); graph-capturable memset node
    void* sc_ptr = nullptr;
    cudaGetSymbolAddress(&sc_ptr, g_scores);
    cudaMemsetAsync(sc_ptr, 0, (size_t)n * sizeof(float));

    int ntiles = (n + TILE96 - 1) / TILE96;
    int grid1 = (nsm < ntiles) ? nsm : ntiles;

    score_kernel<<<grid1, N_THREADS, SMEM_TOTAL>>>(h, W, b, ctx, n);
    seg_stats_kernel<<<B, 128>>>(blk, h_file, alpha);
    int gridB = (n + CHUNK - 1) / CHUNK;
    accum_kernel<<<gridB, 128>>>(h, blk, alpha, h_file, n, B);
}